// round 13
// baseline (speedup 1.0000x reference)
#include <cuda_runtime.h>
#include <cuda_fp16.h>
#include <math.h>

#define NNODES 50000
#define NEDGES 800000
#define NSB ((NNODES + 1023) / 1024)
#define NEB ((NEDGES + 255) / 256)
#define NCB ((NNODES * 256 / 8 + 255) / 256)

// ---------------- scratch (zero-initialized .bss; restored each run) ----------
__device__ int   g_degi[NNODES];
__device__ int   g_count[NNODES];
__device__ int   g_fill[NNODES];
__device__ float g_ls1[NNODES], g_ls2[NNODES];
__device__ float g_s[256];
__device__ int   c_scan, c_sig;
__device__ volatile int c_scan_done;

__device__ float g_dinv[NNODES];
__device__ int   g_rowptr[NNODES + 1];
__device__ int   g_bsum[64];
__device__ int   g_boff[64];
__device__ int2  g_csr[NEDGES];
__device__ __half g_xh [(size_t)NNODES * 256];
__device__ __half g_xah[(size_t)NNODES * 256];
__device__ __half g_hh [(size_t)NNODES * 256];
__device__ __half g_h2h[(size_t)NNODES * 128];
__device__ float g_gamma1[256], g_beta1[256];
__device__ float g_gamma2[128], g_beta2[128];

// ---- bit helpers ----
__device__ __forceinline__ unsigned h2u(__half2 h) {
    union { __half2 h; unsigned u; } c; c.h = h; return c.u;
}
__device__ __forceinline__ __half2 u2h(unsigned u) {
    union { __half2 h; unsigned u; } c; c.u = u; return c.h;
}

__device__ __forceinline__ void mma_f16(float& c0, float& c1, float& c2, float& c3,
                                        unsigned a0, unsigned a1, unsigned a2, unsigned a3,
                                        unsigned b0, unsigned b1)
{
    asm("mma.sync.aligned.m16n8k16.row.col.f32.f16.f16.f32 "
        "{%0,%1,%2,%3},{%4,%5,%6,%7},{%8,%9},{%0,%1,%2,%3};"
        : "+f"(c0), "+f"(c1), "+f"(c2), "+f"(c3)
        : "r"(a0), "r"(a1), "r"(a2), "r"(a3), "r"(b0), "r"(b1));
}

__device__ __forceinline__ void ldsm_x4(unsigned& r0, unsigned& r1,
                                        unsigned& r2, unsigned& r3, unsigned addr)
{
    asm volatile("ldmatrix.sync.aligned.m8n8.x4.shared.b16 {%0,%1,%2,%3}, [%4];"
                 : "=r"(r0), "=r"(r1), "=r"(r2), "=r"(r3) : "r"(addr));
}

// ---------------- degree + histogram + x->fp16 conversion (grid-split) --------
__global__ void k_deg_count(const int* __restrict__ ei, const float* __restrict__ x)
{
    if (blockIdx.x < NEB) {
        int e = blockIdx.x * 256 + threadIdx.x;
        if (e < NEDGES) {
            atomicAdd(&g_degi[ei[e]], 1);
            atomicAdd(&g_count[ei[NEDGES + e]], 1);
        }
        return;
    }
    size_t i = ((size_t)(blockIdx.x - NEB) * 256 + threadIdx.x) * 8;
    if (i < (size_t)NNODES * 256) {
        float4 a = *(const float4*)&x[i];
        float4 b = *(const float4*)&x[i + 4];
        uint4 o;
        o.x = h2u(__float22half2_rn(make_float2(a.x, a.y)));
        o.y = h2u(__float22half2_rn(make_float2(a.z, a.w)));
        o.z = h2u(__float22half2_rn(make_float2(b.x, b.y)));
        o.w = h2u(__float22half2_rn(make_float2(b.z, b.w)));
        *(uint4*)&g_xh[i] = o;
    }
}

// ---------------- scan + CSR fill (fused; all 49 blocks co-resident) ----------
__global__ void k_scan_fill(const int* __restrict__ ei)
{
    __shared__ int sh[1024];
    __shared__ bool isLast;
    int t = threadIdx.x;
    int i = blockIdx.x * 1024 + t;
    if (i < NNODES) g_dinv[i] = rsqrtf(1.0f + (float)g_degi[i]);
    int v = (i < NNODES) ? g_count[i] : 0;
    sh[t] = v;
    __syncthreads();
#pragma unroll
    for (int ofs = 1; ofs < 1024; ofs <<= 1) {
        int a = (t >= ofs) ? sh[t - ofs] : 0;
        __syncthreads();
        sh[t] += a;
        __syncthreads();
    }
    if (i < NNODES) g_rowptr[i] = sh[t] - v;   // block-local exclusive
    if (t == 1023) g_bsum[blockIdx.x] = sh[1023];

    __threadfence();
    if (t == 0) isLast = (atomicAdd(&c_scan, 1) == NSB - 1);
    __syncthreads();
    if (isLast) {
        if (t < 64) sh[t] = (t < NSB) ? g_bsum[t] : 0;
        __syncthreads();
        if (t < 64) {
            int acc = 0;
            for (int k = 0; k < t; k++) acc += sh[k];
            g_boff[t] = acc;
        }
        __syncthreads();
        if (t == 0) {
            c_scan = 0;
            __threadfence();
            c_scan_done = 1;       // release all blocks
        }
    }
    // global barrier: wait for boff
    if (t == 0) {
        while (c_scan_done == 0) { }
    }
    __syncthreads();

    // ---- CSR fill, grid-strided over edges ----
    for (int e = blockIdx.x * 1024 + t; e < NEDGES; e += NSB * 1024) {
        int s = ei[e];
        int d = ei[NEDGES + e];
        int p = g_rowptr[d] + g_boff[d >> 10] + atomicAdd(&g_fill[d], 1);
        float w = g_dinv[s] * g_dinv[d];
        g_csr[p] = make_int2(s, __float_as_int(w));
    }
}

__device__ __forceinline__ int row_beg(int d) { return g_rowptr[d] + g_boff[d >> 10]; }
__device__ __forceinline__ int row_end(int d) {
    return (d + 1 == NNODES) ? NEDGES : g_rowptr[d + 1] + g_boff[(d + 1) >> 10];
}

// ---------------- xa = A @ x  (1 warp/node, 2-edge unroll; 32 regs) -----------
__global__ void __launch_bounds__(256) k_agg1()
{
    int d = blockIdx.x * 8 + (threadIdx.x >> 5);
    int lane = threadIdx.x & 31;
    int c = lane * 8;
    float dv = g_dinv[d];
    float w0 = dv * dv;
    float acc[8];
    {
        uint4 hs = *(const uint4*)&g_xh[(size_t)d * 256 + c];
#pragma unroll
        for (int q = 0; q < 4; q++) {
            float2 f = __half22float2(u2h(((const unsigned*)&hs)[q]));
            acc[2 * q]     = w0 * f.x;
            acc[2 * q + 1] = w0 * f.y;
        }
    }
    int beg = row_beg(d), end = row_end(d);
    int j = beg;
    for (; j + 2 <= end; j += 2) {
        int2 e0 = g_csr[j], e1 = g_csr[j + 1];
        float wa = __int_as_float(e0.y), wb = __int_as_float(e1.y);
        uint4 ha = *(const uint4*)&g_xh[(size_t)e0.x * 256 + c];
        uint4 hb = *(const uint4*)&g_xh[(size_t)e1.x * 256 + c];
#pragma unroll
        for (int q = 0; q < 4; q++) {
            float2 fa = __half22float2(u2h(((const unsigned*)&ha)[q]));
            float2 fb = __half22float2(u2h(((const unsigned*)&hb)[q]));
            acc[2 * q]     += wa * fa.x + wb * fb.x;
            acc[2 * q + 1] += wa * fa.y + wb * fb.y;
        }
    }
    if (j < end) {
        int2 e0 = g_csr[j];
        float wa = __int_as_float(e0.y);
        uint4 ha = *(const uint4*)&g_xh[(size_t)e0.x * 256 + c];
#pragma unroll
        for (int q = 0; q < 4; q++) {
            float2 fa = __half22float2(u2h(((const unsigned*)&ha)[q]));
            acc[2 * q]     += wa * fa.x;
            acc[2 * q + 1] += wa * fa.y;
        }
    }
    uint4 o;
    o.x = h2u(__float22half2_rn(make_float2(acc[0], acc[1])));
    o.y = h2u(__float22half2_rn(make_float2(acc[2], acc[3])));
    o.z = h2u(__float22half2_rn(make_float2(acc[4], acc[5])));
    o.w = h2u(__float22half2_rn(make_float2(acc[6], acc[7])));
    *(uint4*)&g_xah[(size_t)d * 256 + c] = o;
}

// ---------------- fp16 HMMA GEMM (double-buffered, LDSM A-frags) --------------
// MODE 0: A=LN(g_hh), C=g_h2h (N=128)                           [conv2]
// MODE 1: A=g_xah,    C=g_hh (N=256, film+bias+relu, LN stats)  [conv1]
// MODE 2: A=g_xah, no C (N=256, bias+relu -> colsum, + FC heads)[sig]
template <int MODE, int NN>
__global__ void __launch_bounds__(256, 2)
k_gemm(const float* __restrict__ B, const float* __restrict__ bias,
       const float* __restrict__ fc1_w, const float* __restrict__ fc1_b,
       const float* __restrict__ fc2_w, const float* __restrict__ fc2_b,
       const float* __restrict__ fc3_w, const float* __restrict__ fc3_b,
       const float* __restrict__ fc4_w, const float* __restrict__ fc4_b)
{
    const __half* Ah = (MODE == 0) ? g_hh : g_xah;
    __shared__ alignas(16) __half    As[2][128][24];   // pitch 48B -> LDSM conflict-free
    __shared__ alignas(16) unsigned Bs2[2][8][136];    // [k/2][n] half2 pairs
    const int bm = blockIdx.y * 128;
    const int bn = blockIdx.x * 128;
    const int tid = threadIdx.x;

    const int wid = tid >> 5;
    const int wm = wid >> 2;
    const int wn = wid & 3;
    const int lane = tid & 31;
    const int gid = lane >> 2;
    const int tig = lane & 3;

    float acc[4][4][4];
#pragma unroll
    for (int mt = 0; mt < 4; mt++)
#pragma unroll
        for (int nt = 0; nt < 4; nt++)
#pragma unroll
            for (int r = 0; r < 4; r++) acc[mt][nt][r] = 0.0f;

    const int arow = tid >> 1, akh = tid & 1;
    const int ga = bm + arow;
    const bool gaok = (ga < NNODES);
    const int browp = tid >> 5, bq = (tid & 31) * 4;

    const unsigned as_base = (unsigned)__cvta_generic_to_shared(&As[0][0][0]);
    const unsigned lrow = lane & 15;
    const unsigned lkoff = (lane >> 4) * 16;

    uint4 areg;
    float4 breg0, breg1;
    float mu = 0.f, rs = 0.f;
    if (MODE == 0 && gaok) {
        float s1 = g_ls1[ga], s2 = g_ls2[ga];
        mu = s1 * (1.0f / 256.0f);
        rs = rsqrtf(s2 * (1.0f / 256.0f) - mu * mu + 1e-5f);
    }

    auto load_tile = [&](int k0) {
        areg = make_uint4(0, 0, 0, 0);
        if (gaok) areg = *(const uint4*)&Ah[(size_t)ga * 256 + k0 + akh * 8];
        breg0 = *(const float4*)&B[(size_t)(k0 + 2 * browp) * NN + bn + bq];
        breg1 = *(const float4*)&B[(size_t)(k0 + 2 * browp + 1) * NN + bn + bq];
    };
    auto stage = [&](int buf) {
        uint4 av = areg;
        if (MODE == 0) {
#pragma unroll
            for (int q = 0; q < 4; q++) {
                float2 f = __half22float2(u2h(((const unsigned*)&av)[q]));
                f.x = (f.x - mu) * rs;
                f.y = (f.y - mu) * rs;
                ((unsigned*)&av)[q] = h2u(__float22half2_rn(f));
            }
        }
        *(uint4*)&As[buf][arow][akh * 8] = av;
        uint4 bv;
        bv.x = h2u(__float22half2_rn(make_float2(breg0.x, breg1.x)));
        bv.y = h2u(__float22half2_rn(make_float2(breg0.y, breg1.y)));
        bv.z = h2u(__float22half2_rn(make_float2(breg0.z, breg1.z)));
        bv.w = h2u(__float22half2_rn(make_float2(breg0.w, breg1.w)));
        *(uint4*)&Bs2[buf][browp][bq] = bv;
    };

    load_tile(0);
    stage(0);
    load_tile(16);
    __syncthreads();

    const int NT = 256 / 16;
    for (int t = 0; t < NT; t++) {
        int cur = t & 1;
        if (t + 1 < NT) stage(cur ^ 1);
        if (t + 2 < NT) load_tile((t + 2) * 16);

        unsigned af[4][4], bf[4][2];
        const unsigned as_cur = as_base + (unsigned)(cur * 128 * 48);
#pragma unroll
        for (int mt = 0; mt < 4; mt++) {
            unsigned row = (unsigned)(wm * 64 + mt * 16) + lrow;
            unsigned addr = as_cur + row * 48u + lkoff;
            ldsm_x4(af[mt][0], af[mt][1], af[mt][2], af[mt][3], addr);
        }
#pragma unroll
        for (int nt = 0; nt < 4; nt++) {
            int nc = wn * 32 + nt * 8 + gid;
            bf[nt][0] = Bs2[cur][tig][nc];
            bf[nt][1] = Bs2[cur][tig + 4][nc];
        }
#pragma unroll
        for (int mt = 0; mt < 4; mt++)
#pragma unroll
            for (int nt = 0; nt < 4; nt++)
                mma_f16(acc[mt][nt][0], acc[mt][nt][1], acc[mt][nt][2], acc[mt][nt][3],
                        af[mt][0], af[mt][1], af[mt][2], af[mt][3],
                        bf[nt][0], bf[nt][1]);
        __syncthreads();
    }

    // ---------------- epilogues ----------------
    if (MODE == 0) {
#pragma unroll
        for (int mt = 0; mt < 4; mt++) {
            int r0 = bm + wm * 64 + mt * 16 + gid;
            int r1 = r0 + 8;
#pragma unroll
            for (int nt = 0; nt < 4; nt++) {
                int c = wn * 32 + nt * 8 + tig * 2;
                if (r0 < NNODES) {
                    __half2 o = __float22half2_rn(make_float2(acc[mt][nt][0], acc[mt][nt][1]));
                    *(__half2*)&g_h2h[(size_t)r0 * 128 + c] = o;
                }
                if (r1 < NNODES) {
                    __half2 o = __float22half2_rn(make_float2(acc[mt][nt][2], acc[mt][nt][3]));
                    *(__half2*)&g_h2h[(size_t)r1 * 128 + c] = o;
                }
            }
        }
    }
    if (MODE == 1) {
        float ga2[4][2], be[4][2];
#pragma unroll
        for (int nt = 0; nt < 4; nt++) {
            int c = bn + wn * 32 + nt * 8 + tig * 2;
            ga2[nt][0] = g_gamma1[c];     be[nt][0] = g_beta1[c] + bias[c];
            ga2[nt][1] = g_gamma1[c + 1]; be[nt][1] = g_beta1[c + 1] + bias[c + 1];
        }
#pragma unroll
        for (int mt = 0; mt < 4; mt++) {
            int r0 = bm + wm * 64 + mt * 16 + gid;
            int r1 = r0 + 8;
            float s1a = 0.f, s2a = 0.f, s1b = 0.f, s2b = 0.f;
#pragma unroll
            for (int nt = 0; nt < 4; nt++) {
                int c = bn + wn * 32 + nt * 8 + tig * 2;
                float o0 = fmaxf(ga2[nt][0] * acc[mt][nt][0] + be[nt][0], 0.f);
                float o1 = fmaxf(ga2[nt][1] * acc[mt][nt][1] + be[nt][1], 0.f);
                float o2 = fmaxf(ga2[nt][0] * acc[mt][nt][2] + be[nt][0], 0.f);
                float o3 = fmaxf(ga2[nt][1] * acc[mt][nt][3] + be[nt][1], 0.f);
                if (r0 < NNODES)
                    *(__half2*)&g_hh[(size_t)r0 * 256 + c] =
                        __float22half2_rn(make_float2(o0, o1));
                if (r1 < NNODES)
                    *(__half2*)&g_hh[(size_t)r1 * 256 + c] =
                        __float22half2_rn(make_float2(o2, o3));
                s1a += o0 + o1;  s2a += o0 * o0 + o1 * o1;
                s1b += o2 + o3;  s2b += o2 * o2 + o3 * o3;
            }
            s1a += __shfl_xor_sync(0xffffffffu, s1a, 1);
            s1a += __shfl_xor_sync(0xffffffffu, s1a, 2);
            s2a += __shfl_xor_sync(0xffffffffu, s2a, 1);
            s2a += __shfl_xor_sync(0xffffffffu, s2a, 2);
            s1b += __shfl_xor_sync(0xffffffffu, s1b, 1);
            s1b += __shfl_xor_sync(0xffffffffu, s1b, 2);
            s2b += __shfl_xor_sync(0xffffffffu, s2b, 1);
            s2b += __shfl_xor_sync(0xffffffffu, s2b, 2);
            if (tig == 0) {
                if (r0 < NNODES) {
                    atomicAdd(&g_ls1[r0], s1a);
                    atomicAdd(&g_ls2[r0], s2a);
                }
                if (r1 < NNODES) {
                    atomicAdd(&g_ls1[r1], s1b);
                    atomicAdd(&g_ls2[r1], s2b);
                }
            }
        }
    }
    if (MODE == 2) {
#pragma unroll
        for (int nt = 0; nt < 4; nt++) {
            int c = bn + wn * 32 + nt * 8 + tig * 2;
            float b0 = bias[c], b1 = bias[c + 1];
            float p0 = 0.f, p1 = 0.f;
#pragma unroll
            for (int mt = 0; mt < 4; mt++) {
                int r0 = bm + wm * 64 + mt * 16 + gid;
                int r1 = r0 + 8;
                if (r0 < NNODES) {
                    p0 += fmaxf(acc[mt][nt][0] + b0, 0.f);
                    p1 += fmaxf(acc[mt][nt][1] + b1, 0.f);
                }
                if (r1 < NNODES) {
                    p0 += fmaxf(acc[mt][nt][2] + b0, 0.f);
                    p1 += fmaxf(acc[mt][nt][3] + b1, 0.f);
                }
            }
#pragma unroll
            for (int o = 4; o <= 16; o <<= 1) {
                p0 += __shfl_xor_sync(0xffffffffu, p0, o);
                p1 += __shfl_xor_sync(0xffffffffu, p1, o);
            }
            if (gid == 0) {
                atomicAdd(&g_s[c], p0);
                atomicAdd(&g_s[c + 1], p1);
            }
        }
        __shared__ bool isLast;
        __shared__ float sh_s[256];
        __threadfence();
        if (tid == 0) isLast = (atomicAdd(&c_sig, 1) == 2 * 391 - 1);
        __syncthreads();
        if (isLast) {
            sh_s[tid] = g_s[tid];
            __syncthreads();
            float a1 = fc1_b[tid], a2 = fc2_b[tid];
            float a3 = (tid < 128) ? fc3_b[tid] : 0.f;
            float a4 = (tid < 128) ? fc4_b[tid] : 0.f;
            for (int k = 0; k < 256; k++) {
                float sv = sh_s[k];
                a1 += fc1_w[tid * 256 + k] * sv;
                a2 += fc2_w[tid * 256 + k] * sv;
                if (tid < 128) {
                    a3 += fc3_w[tid * 256 + k] * sv;
                    a4 += fc4_w[tid * 256 + k] * sv;
                }
            }
            g_gamma1[tid] = tanhf(a1);
            g_beta1[tid]  = tanhf(a2);
            if (tid < 128) {
                g_gamma2[tid] = tanhf(a3);
                g_beta2[tid]  = tanhf(a4);
            }
            g_s[tid] = 0.0f;
            if (tid == 0) c_sig = 0;
        }
    }
}

// ---------------- final: agg(h2 fp16) + film + LN; tail blocks clean scratch --
__global__ void __launch_bounds__(256) k_agg2(const float* __restrict__ bias,
                                              float* __restrict__ out)
{
    if (blockIdx.x >= NNODES / 8) {
        int cb = blockIdx.x - NNODES / 8;
        int stride = 64 * 256;
        for (int i = cb * 256 + threadIdx.x; i < NNODES; i += stride) {
            g_degi[i] = 0;
            g_count[i] = 0;
            g_fill[i] = 0;
            g_ls1[i] = 0.0f;
            g_ls2[i] = 0.0f;
        }
        if (cb == 0 && threadIdx.x == 0) c_scan_done = 0;   // reset barrier flag
        return;
    }
    int d = blockIdx.x * 8 + (threadIdx.x >> 5);
    int lane = threadIdx.x & 31;
    int c = lane * 4;
    float dv = g_dinv[d];
    float w0 = dv * dv;
    float4 acc;
    {
        uint2 hv = *(const uint2*)&g_h2h[(size_t)d * 128 + c];
        float2 f0 = __half22float2(u2h(hv.x));
        float2 f1 = __half22float2(u2h(hv.y));
        acc = make_float4(w0 * f0.x, w0 * f0.y, w0 * f1.x, w0 * f1.y);
    }
    int beg = row_beg(d), end = row_end(d);
    int j = beg;
    for (; j + 2 <= end; j += 2) {
        int2 e0 = g_csr[j], e1 = g_csr[j + 1];
        float wa = __int_as_float(e0.y), wb = __int_as_float(e1.y);
        uint2 ha = *(const uint2*)&g_h2h[(size_t)e0.x * 128 + c];
        uint2 hb = *(const uint2*)&g_h2h[(size_t)e1.x * 128 + c];
        float2 a0 = __half22float2(u2h(ha.x));
        float2 a1 = __half22float2(u2h(ha.y));
        float2 b0 = __half22float2(u2h(hb.x));
        float2 b1 = __half22float2(u2h(hb.y));
        acc.x += wa * a0.x + wb * b0.x;
        acc.y += wa * a0.y + wb * b0.y;
        acc.z += wa * a1.x + wb * b1.x;
        acc.w += wa * a1.y + wb * b1.y;
    }
    if (j < end) {
        int2 e0 = g_csr[j];
        float wa = __int_as_float(e0.y);
        uint2 ha = *(const uint2*)&g_h2h[(size_t)e0.x * 128 + c];
        float2 a0 = __half22float2(u2h(ha.x));
        float2 a1 = __half22float2(u2h(ha.y));
        acc.x += wa * a0.x; acc.y += wa * a0.y;
        acc.z += wa * a1.x; acc.w += wa * a1.y;
    }
    float4 y;
    y.x = g_gamma2[c + 0] * acc.x + g_beta2[c + 0] + bias[c + 0];
    y.y = g_gamma2[c + 1] * acc.y + g_beta2[c + 1] + bias[c + 1];
    y.z = g_gamma2[c + 2] * acc.z + g_beta2[c + 2] + bias[c + 2];
    y.w = g_gamma2[c + 3] * acc.w + g_beta2[c + 3] + bias[c + 3];

    float s1 = y.x + y.y + y.z + y.w;
    float s2 = y.x * y.x + y.y * y.y + y.z * y.z + y.w * y.w;
#pragma unroll
    for (int o = 16; o; o >>= 1) {
        s1 += __shfl_xor_sync(0xffffffffu, s1, o);
        s2 += __shfl_xor_sync(0xffffffffu, s2, o);
    }
    float mu = s1 * (1.0f / 128.0f);
    float var = s2 * (1.0f / 128.0f) - mu * mu;
    float rstd = rsqrtf(var + 1e-5f);
    float4 o4;
    o4.x = (y.x - mu) * rstd;
    o4.y = (y.y - mu) * rstd;
    o4.z = (y.z - mu) * rstd;
    o4.w = (y.w - mu) * rstd;
    *(float4*)&out[(size_t)d * 128 + c] = o4;
}

// ---------------- launch ----------------
extern "C" void kernel_launch(void* const* d_in, const int* in_sizes, int n_in,
                              void* d_out, int out_size)
{
    const float* x       = (const float*)d_in[0];
    const int*   ei      = (const int*)d_in[1];
    const float* conv1_w = (const float*)d_in[2];
    const float* conv1_b = (const float*)d_in[3];
    const float* conv2_w = (const float*)d_in[4];
    const float* conv2_b = (const float*)d_in[5];
    const float* sig_w   = (const float*)d_in[6];
    const float* sig_b   = (const float*)d_in[7];
    const float* fc1_w   = (const float*)d_in[8];
    const float* fc1_b   = (const float*)d_in[9];
    const float* fc2_w   = (const float*)d_in[10];
    const float* fc2_b   = (const float*)d_in[11];
    const float* fc3_w   = (const float*)d_in[12];
    const float* fc3_b   = (const float*)d_in[13];
    const float* fc4_w   = (const float*)d_in[14];
    const float* fc4_b   = (const float*)d_in[15];
    float*       out     = (float*)d_out;

    k_deg_count<<<NEB + NCB, 256>>>(ei, x);
    k_scan_fill<<<NSB, 1024>>>(ei);
    k_agg1<<<NNODES / 8, 256>>>();

    dim3 g256(2, (NNODES + 127) / 128);
    dim3 g128(1, (NNODES + 127) / 128);

    k_gemm<2, 256><<<g256, 256>>>(sig_w, sig_b,
                                  fc1_w, fc1_b, fc2_w, fc2_b,
                                  fc3_w, fc3_b, fc4_w, fc4_b);
    k_gemm<1, 256><<<g256, 256>>>(conv1_w, conv1_b,
                                  nullptr, nullptr, nullptr, nullptr,
                                  nullptr, nullptr, nullptr, nullptr);
    k_gemm<0, 128><<<g128, 256>>>(conv2_w, nullptr,
                                  nullptr, nullptr, nullptr, nullptr,
                                  nullptr, nullptr, nullptr, nullptr);
    k_agg2<<<NNODES / 8 + 64, 256>>>(conv2_b, out);
}

// round 14
// speedup vs baseline: 1.0963x; 1.0963x over previous
#include <cuda_runtime.h>
#include <cuda_fp16.h>
#include <math.h>

#define NNODES 50000
#define NEDGES 800000
#define NSB ((NNODES + 1023) / 1024)
#define NEB ((NEDGES + 255) / 256)
#define NCB ((NNODES * 256 / 8 + 255) / 256)

// ---------------- scratch (zero-initialized .bss; restored each run) ----------
__device__ int   g_degi[NNODES];
__device__ int   g_count[NNODES];
__device__ int   g_fill[NNODES];
__device__ float g_ls1[NNODES], g_ls2[NNODES];
__device__ float g_s[256];
__device__ int   c_scan, c_sig;

__device__ float g_dinv[NNODES];
__device__ int   g_rowptr[NNODES + 1];
__device__ int   g_bsum[64];
__device__ int   g_boff[64];
__device__ int2  g_csr[NEDGES];
__device__ __half g_xh [(size_t)NNODES * 256];
__device__ __half g_xah[(size_t)NNODES * 256];
__device__ __half g_hh [(size_t)NNODES * 256];
__device__ __half g_h2h[(size_t)NNODES * 128];
__device__ float g_gamma1[256], g_beta1[256];
__device__ float g_gamma2[128], g_beta2[128];

// ---- bit helpers ----
__device__ __forceinline__ unsigned h2u(__half2 h) {
    union { __half2 h; unsigned u; } c; c.h = h; return c.u;
}
__device__ __forceinline__ __half2 u2h(unsigned u) {
    union { __half2 h; unsigned u; } c; c.u = u; return c.h;
}

__device__ __forceinline__ void mma_f16(float& c0, float& c1, float& c2, float& c3,
                                        unsigned a0, unsigned a1, unsigned a2, unsigned a3,
                                        unsigned b0, unsigned b1)
{
    asm("mma.sync.aligned.m16n8k16.row.col.f32.f16.f16.f32 "
        "{%0,%1,%2,%3},{%4,%5,%6,%7},{%8,%9},{%0,%1,%2,%3};"
        : "+f"(c0), "+f"(c1), "+f"(c2), "+f"(c3)
        : "r"(a0), "r"(a1), "r"(a2), "r"(a3), "r"(b0), "r"(b1));
}

__device__ __forceinline__ void ldsm_x4(unsigned& r0, unsigned& r1,
                                        unsigned& r2, unsigned& r3, unsigned addr)
{
    asm volatile("ldmatrix.sync.aligned.m8n8.x4.shared.b16 {%0,%1,%2,%3}, [%4];"
                 : "=r"(r0), "=r"(r1), "=r"(r2), "=r"(r3) : "r"(addr));
}

// ---------------- degree + histogram + x->fp16 conversion (grid-split) --------
__global__ void k_deg_count(const int* __restrict__ ei, const float* __restrict__ x)
{
    if (blockIdx.x < NEB) {
        int e = blockIdx.x * 256 + threadIdx.x;
        if (e < NEDGES) {
            atomicAdd(&g_degi[ei[e]], 1);
            atomicAdd(&g_count[ei[NEDGES + e]], 1);
        }
        return;
    }
    size_t i = ((size_t)(blockIdx.x - NEB) * 256 + threadIdx.x) * 8;
    if (i < (size_t)NNODES * 256) {
        float4 a = *(const float4*)&x[i];
        float4 b = *(const float4*)&x[i + 4];
        uint4 o;
        o.x = h2u(__float22half2_rn(make_float2(a.x, a.y)));
        o.y = h2u(__float22half2_rn(make_float2(a.z, a.w)));
        o.z = h2u(__float22half2_rn(make_float2(b.x, b.y)));
        o.w = h2u(__float22half2_rn(make_float2(b.z, b.w)));
        *(uint4*)&g_xh[i] = o;
    }
}

// ---------------- scan (local scan + dinv; last block reduces block sums) -----
__global__ void k_scan1()
{
    __shared__ int sh[1024];
    __shared__ bool isLast;
    int t = threadIdx.x;
    int i = blockIdx.x * 1024 + t;
    if (i < NNODES) g_dinv[i] = rsqrtf(1.0f + (float)g_degi[i]);
    int v = (i < NNODES) ? g_count[i] : 0;
    sh[t] = v;
    __syncthreads();
#pragma unroll
    for (int ofs = 1; ofs < 1024; ofs <<= 1) {
        int a = (t >= ofs) ? sh[t - ofs] : 0;
        __syncthreads();
        sh[t] += a;
        __syncthreads();
    }
    if (i < NNODES) g_rowptr[i] = sh[t] - v;
    if (t == 1023) g_bsum[blockIdx.x] = sh[1023];

    __threadfence();
    if (t == 0) isLast = (atomicAdd(&c_scan, 1) == NSB - 1);
    __syncthreads();
    if (isLast) {
        if (t < 64) sh[t] = (t < NSB) ? g_bsum[t] : 0;
        __syncthreads();
        if (t < 64) {
            int acc = 0;
            for (int k = 0; k < t; k++) acc += sh[k];
            g_boff[t] = acc;
        }
        if (t == 0) c_scan = 0;
    }
}

__device__ __forceinline__ int row_beg(int d) { return g_rowptr[d] + g_boff[d >> 10]; }
__device__ __forceinline__ int row_end(int d) {
    return (d + 1 == NNODES) ? NEDGES : g_rowptr[d + 1] + g_boff[(d + 1) >> 10];
}

// ---------------- CSR fill (1 edge/thread -> max MLP on random atomics) -------
__global__ void k_fill(const int* __restrict__ ei)
{
    int e = blockIdx.x * blockDim.x + threadIdx.x;
    if (e < NEDGES) {
        int s = ei[e];
        int d = ei[NEDGES + e];
        int p = g_rowptr[d] + g_boff[d >> 10] + atomicAdd(&g_fill[d], 1);
        float w = g_dinv[s] * g_dinv[d];
        g_csr[p] = make_int2(s, __float_as_int(w));
    }
}

// ---------------- xa = A @ x  (1 warp/node, 2-edge unroll; 32 regs) -----------
__global__ void __launch_bounds__(256) k_agg1()
{
    int d = blockIdx.x * 8 + (threadIdx.x >> 5);
    int lane = threadIdx.x & 31;
    int c = lane * 8;
    float dv = g_dinv[d];
    float w0 = dv * dv;
    float acc[8];
    {
        uint4 hs = *(const uint4*)&g_xh[(size_t)d * 256 + c];
#pragma unroll
        for (int q = 0; q < 4; q++) {
            float2 f = __half22float2(u2h(((const unsigned*)&hs)[q]));
            acc[2 * q]     = w0 * f.x;
            acc[2 * q + 1] = w0 * f.y;
        }
    }
    int beg = row_beg(d), end = row_end(d);
    int j = beg;
    for (; j + 2 <= end; j += 2) {
        int2 e0 = g_csr[j], e1 = g_csr[j + 1];
        float wa = __int_as_float(e0.y), wb = __int_as_float(e1.y);
        uint4 ha = *(const uint4*)&g_xh[(size_t)e0.x * 256 + c];
        uint4 hb = *(const uint4*)&g_xh[(size_t)e1.x * 256 + c];
#pragma unroll
        for (int q = 0; q < 4; q++) {
            float2 fa = __half22float2(u2h(((const unsigned*)&ha)[q]));
            float2 fb = __half22float2(u2h(((const unsigned*)&hb)[q]));
            acc[2 * q]     += wa * fa.x + wb * fb.x;
            acc[2 * q + 1] += wa * fa.y + wb * fb.y;
        }
    }
    if (j < end) {
        int2 e0 = g_csr[j];
        float wa = __int_as_float(e0.y);
        uint4 ha = *(const uint4*)&g_xh[(size_t)e0.x * 256 + c];
#pragma unroll
        for (int q = 0; q < 4; q++) {
            float2 fa = __half22float2(u2h(((const unsigned*)&ha)[q]));
            acc[2 * q]     += wa * fa.x;
            acc[2 * q + 1] += wa * fa.y;
        }
    }
    uint4 o;
    o.x = h2u(__float22half2_rn(make_float2(acc[0], acc[1])));
    o.y = h2u(__float22half2_rn(make_float2(acc[2], acc[3])));
    o.z = h2u(__float22half2_rn(make_float2(acc[4], acc[5])));
    o.w = h2u(__float22half2_rn(make_float2(acc[6], acc[7])));
    *(uint4*)&g_xah[(size_t)d * 256 + c] = o;
}

// ---------------- fp16 HMMA GEMM (double-buffered, LDSM A-frags) --------------
// MODE 0: A=LN(g_hh), C=g_h2h (N=128)                           [conv2]
// MODE 1: A=g_xah,    C=g_hh (N=256, film+bias+relu, LN stats)  [conv1]
// MODE 2: A=g_xah, no C (N=256, bias+relu -> colsum, + FC heads)[sig]
template <int MODE, int NN>
__global__ void __launch_bounds__(256, 2)
k_gemm(const float* __restrict__ B, const float* __restrict__ bias,
       const float* __restrict__ fc1_w, const float* __restrict__ fc1_b,
       const float* __restrict__ fc2_w, const float* __restrict__ fc2_b,
       const float* __restrict__ fc3_w, const float* __restrict__ fc3_b,
       const float* __restrict__ fc4_w, const float* __restrict__ fc4_b)
{
    const __half* Ah = (MODE == 0) ? g_hh : g_xah;
    __shared__ alignas(16) __half    As[2][128][24];   // pitch 48B -> LDSM conflict-free
    __shared__ alignas(16) unsigned Bs2[2][8][136];    // [k/2][n] half2 pairs
    const int bm = blockIdx.y * 128;
    const int bn = blockIdx.x * 128;
    const int tid = threadIdx.x;

    const int wid = tid >> 5;
    const int wm = wid >> 2;
    const int wn = wid & 3;
    const int lane = tid & 31;
    const int gid = lane >> 2;
    const int tig = lane & 3;

    float acc[4][4][4];
#pragma unroll
    for (int mt = 0; mt < 4; mt++)
#pragma unroll
        for (int nt = 0; nt < 4; nt++)
#pragma unroll
            for (int r = 0; r < 4; r++) acc[mt][nt][r] = 0.0f;

    const int arow = tid >> 1, akh = tid & 1;
    const int ga = bm + arow;
    const bool gaok = (ga < NNODES);
    const int browp = tid >> 5, bq = (tid & 31) * 4;

    const unsigned as_base = (unsigned)__cvta_generic_to_shared(&As[0][0][0]);
    const unsigned lrow = lane & 15;
    const unsigned lkoff = (lane >> 4) * 16;

    uint4 areg;
    float4 breg0, breg1;
    float mu = 0.f, rs = 0.f;
    if (MODE == 0 && gaok) {
        float s1 = g_ls1[ga], s2 = g_ls2[ga];
        mu = s1 * (1.0f / 256.0f);
        rs = rsqrtf(s2 * (1.0f / 256.0f) - mu * mu + 1e-5f);
    }

    auto load_tile = [&](int k0) {
        areg = make_uint4(0, 0, 0, 0);
        if (gaok) areg = *(const uint4*)&Ah[(size_t)ga * 256 + k0 + akh * 8];
        breg0 = *(const float4*)&B[(size_t)(k0 + 2 * browp) * NN + bn + bq];
        breg1 = *(const float4*)&B[(size_t)(k0 + 2 * browp + 1) * NN + bn + bq];
    };
    auto stage = [&](int buf) {
        uint4 av = areg;
        if (MODE == 0) {
#pragma unroll
            for (int q = 0; q < 4; q++) {
                float2 f = __half22float2(u2h(((const unsigned*)&av)[q]));
                f.x = (f.x - mu) * rs;
                f.y = (f.y - mu) * rs;
                ((unsigned*)&av)[q] = h2u(__float22half2_rn(f));
            }
        }
        *(uint4*)&As[buf][arow][akh * 8] = av;
        uint4 bv;
        bv.x = h2u(__float22half2_rn(make_float2(breg0.x, breg1.x)));
        bv.y = h2u(__float22half2_rn(make_float2(breg0.y, breg1.y)));
        bv.z = h2u(__float22half2_rn(make_float2(breg0.z, breg1.z)));
        bv.w = h2u(__float22half2_rn(make_float2(breg0.w, breg1.w)));
        *(uint4*)&Bs2[buf][browp][bq] = bv;
    };

    load_tile(0);
    stage(0);
    load_tile(16);
    __syncthreads();

    const int NT = 256 / 16;
    for (int t = 0; t < NT; t++) {
        int cur = t & 1;
        if (t + 1 < NT) stage(cur ^ 1);
        if (t + 2 < NT) load_tile((t + 2) * 16);

        unsigned af[4][4], bf[4][2];
        const unsigned as_cur = as_base + (unsigned)(cur * 128 * 48);
#pragma unroll
        for (int mt = 0; mt < 4; mt++) {
            unsigned row = (unsigned)(wm * 64 + mt * 16) + lrow;
            unsigned addr = as_cur + row * 48u + lkoff;
            ldsm_x4(af[mt][0], af[mt][1], af[mt][2], af[mt][3], addr);
        }
#pragma unroll
        for (int nt = 0; nt < 4; nt++) {
            int nc = wn * 32 + nt * 8 + gid;
            bf[nt][0] = Bs2[cur][tig][nc];
            bf[nt][1] = Bs2[cur][tig + 4][nc];
        }
#pragma unroll
        for (int mt = 0; mt < 4; mt++)
#pragma unroll
            for (int nt = 0; nt < 4; nt++)
                mma_f16(acc[mt][nt][0], acc[mt][nt][1], acc[mt][nt][2], acc[mt][nt][3],
                        af[mt][0], af[mt][1], af[mt][2], af[mt][3],
                        bf[nt][0], bf[nt][1]);
        __syncthreads();
    }

    // ---------------- epilogues ----------------
    if (MODE == 0) {
#pragma unroll
        for (int mt = 0; mt < 4; mt++) {
            int r0 = bm + wm * 64 + mt * 16 + gid;
            int r1 = r0 + 8;
#pragma unroll
            for (int nt = 0; nt < 4; nt++) {
                int c = wn * 32 + nt * 8 + tig * 2;
                if (r0 < NNODES) {
                    __half2 o = __float22half2_rn(make_float2(acc[mt][nt][0], acc[mt][nt][1]));
                    *(__half2*)&g_h2h[(size_t)r0 * 128 + c] = o;
                }
                if (r1 < NNODES) {
                    __half2 o = __float22half2_rn(make_float2(acc[mt][nt][2], acc[mt][nt][3]));
                    *(__half2*)&g_h2h[(size_t)r1 * 128 + c] = o;
                }
            }
        }
    }
    if (MODE == 1) {
        float ga2[4][2], be[4][2];
#pragma unroll
        for (int nt = 0; nt < 4; nt++) {
            int c = bn + wn * 32 + nt * 8 + tig * 2;
            ga2[nt][0] = g_gamma1[c];     be[nt][0] = g_beta1[c] + bias[c];
            ga2[nt][1] = g_gamma1[c + 1]; be[nt][1] = g_beta1[c + 1] + bias[c + 1];
        }
#pragma unroll
        for (int mt = 0; mt < 4; mt++) {
            int r0 = bm + wm * 64 + mt * 16 + gid;
            int r1 = r0 + 8;
            float s1a = 0.f, s2a = 0.f, s1b = 0.f, s2b = 0.f;
#pragma unroll
            for (int nt = 0; nt < 4; nt++) {
                int c = bn + wn * 32 + nt * 8 + tig * 2;
                float o0 = fmaxf(ga2[nt][0] * acc[mt][nt][0] + be[nt][0], 0.f);
                float o1 = fmaxf(ga2[nt][1] * acc[mt][nt][1] + be[nt][1], 0.f);
                float o2 = fmaxf(ga2[nt][0] * acc[mt][nt][2] + be[nt][0], 0.f);
                float o3 = fmaxf(ga2[nt][1] * acc[mt][nt][3] + be[nt][1], 0.f);
                if (r0 < NNODES)
                    *(__half2*)&g_hh[(size_t)r0 * 256 + c] =
                        __float22half2_rn(make_float2(o0, o1));
                if (r1 < NNODES)
                    *(__half2*)&g_hh[(size_t)r1 * 256 + c] =
                        __float22half2_rn(make_float2(o2, o3));
                s1a += o0 + o1;  s2a += o0 * o0 + o1 * o1;
                s1b += o2 + o3;  s2b += o2 * o2 + o3 * o3;
            }
            s1a += __shfl_xor_sync(0xffffffffu, s1a, 1);
            s1a += __shfl_xor_sync(0xffffffffu, s1a, 2);
            s2a += __shfl_xor_sync(0xffffffffu, s2a, 1);
            s2a += __shfl_xor_sync(0xffffffffu, s2a, 2);
            s1b += __shfl_xor_sync(0xffffffffu, s1b, 1);
            s1b += __shfl_xor_sync(0xffffffffu, s1b, 2);
            s2b += __shfl_xor_sync(0xffffffffu, s2b, 1);
            s2b += __shfl_xor_sync(0xffffffffu, s2b, 2);
            if (tig == 0) {
                if (r0 < NNODES) {
                    atomicAdd(&g_ls1[r0], s1a);
                    atomicAdd(&g_ls2[r0], s2a);
                }
                if (r1 < NNODES) {
                    atomicAdd(&g_ls1[r1], s1b);
                    atomicAdd(&g_ls2[r1], s2b);
                }
            }
        }
    }
    if (MODE == 2) {
#pragma unroll
        for (int nt = 0; nt < 4; nt++) {
            int c = bn + wn * 32 + nt * 8 + tig * 2;
            float b0 = bias[c], b1 = bias[c + 1];
            float p0 = 0.f, p1 = 0.f;
#pragma unroll
            for (int mt = 0; mt < 4; mt++) {
                int r0 = bm + wm * 64 + mt * 16 + gid;
                int r1 = r0 + 8;
                if (r0 < NNODES) {
                    p0 += fmaxf(acc[mt][nt][0] + b0, 0.f);
                    p1 += fmaxf(acc[mt][nt][1] + b1, 0.f);
                }
                if (r1 < NNODES) {
                    p0 += fmaxf(acc[mt][nt][2] + b0, 0.f);
                    p1 += fmaxf(acc[mt][nt][3] + b1, 0.f);
                }
            }
#pragma unroll
            for (int o = 4; o <= 16; o <<= 1) {
                p0 += __shfl_xor_sync(0xffffffffu, p0, o);
                p1 += __shfl_xor_sync(0xffffffffu, p1, o);
            }
            if (gid == 0) {
                atomicAdd(&g_s[c], p0);
                atomicAdd(&g_s[c + 1], p1);
            }
        }
        __shared__ bool isLast;
        __shared__ float sh_s[256];
        __threadfence();
        if (tid == 0) isLast = (atomicAdd(&c_sig, 1) == 2 * 391 - 1);
        __syncthreads();
        if (isLast) {
            sh_s[tid] = g_s[tid];
            __syncthreads();
            float a1 = fc1_b[tid], a2 = fc2_b[tid];
            float a3 = (tid < 128) ? fc3_b[tid] : 0.f;
            float a4 = (tid < 128) ? fc4_b[tid] : 0.f;
            for (int k = 0; k < 256; k++) {
                float sv = sh_s[k];
                a1 += fc1_w[tid * 256 + k] * sv;
                a2 += fc2_w[tid * 256 + k] * sv;
                if (tid < 128) {
                    a3 += fc3_w[tid * 256 + k] * sv;
                    a4 += fc4_w[tid * 256 + k] * sv;
                }
            }
            g_gamma1[tid] = tanhf(a1);
            g_beta1[tid]  = tanhf(a2);
            if (tid < 128) {
                g_gamma2[tid] = tanhf(a3);
                g_beta2[tid]  = tanhf(a4);
            }
            g_s[tid] = 0.0f;
            if (tid == 0) c_sig = 0;
        }
    }
}

// ---------------- final: agg(h2 fp16) + film + LN; tail blocks clean scratch --
__global__ void __launch_bounds__(256) k_agg2(const float* __restrict__ bias,
                                              float* __restrict__ out)
{
    if (blockIdx.x >= NNODES / 8) {
        int cb = blockIdx.x - NNODES / 8;
        int stride = 64 * 256;
        for (int i = cb * 256 + threadIdx.x; i < NNODES; i += stride) {
            g_degi[i] = 0;
            g_count[i] = 0;
            g_fill[i] = 0;
            g_ls1[i] = 0.0f;
            g_ls2[i] = 0.0f;
        }
        return;
    }
    int d = blockIdx.x * 8 + (threadIdx.x >> 5);
    int lane = threadIdx.x & 31;
    int c = lane * 4;
    float dv = g_dinv[d];
    float w0 = dv * dv;
    float4 acc;
    {
        uint2 hv = *(const uint2*)&g_h2h[(size_t)d * 128 + c];
        float2 f0 = __half22float2(u2h(hv.x));
        float2 f1 = __half22float2(u2h(hv.y));
        acc = make_float4(w0 * f0.x, w0 * f0.y, w0 * f1.x, w0 * f1.y);
    }
    int beg = row_beg(d), end = row_end(d);
    int j = beg;
    for (; j + 2 <= end; j += 2) {
        int2 e0 = g_csr[j], e1 = g_csr[j + 1];
        float wa = __int_as_float(e0.y), wb = __int_as_float(e1.y);
        uint2 ha = *(const uint2*)&g_h2h[(size_t)e0.x * 128 + c];
        uint2 hb = *(const uint2*)&g_h2h[(size_t)e1.x * 128 + c];
        float2 a0 = __half22float2(u2h(ha.x));
        float2 a1 = __half22float2(u2h(ha.y));
        float2 b0 = __half22float2(u2h(hb.x));
        float2 b1 = __half22float2(u2h(hb.y));
        acc.x += wa * a0.x + wb * b0.x;
        acc.y += wa * a0.y + wb * b0.y;
        acc.z += wa * a1.x + wb * b1.x;
        acc.w += wa * a1.y + wb * b1.y;
    }
    if (j < end) {
        int2 e0 = g_csr[j];
        float wa = __int_as_float(e0.y);
        uint2 ha = *(const uint2*)&g_h2h[(size_t)e0.x * 128 + c];
        float2 a0 = __half22float2(u2h(ha.x));
        float2 a1 = __half22float2(u2h(ha.y));
        acc.x += wa * a0.x; acc.y += wa * a0.y;
        acc.z += wa * a1.x; acc.w += wa * a1.y;
    }
    float4 y;
    y.x = g_gamma2[c + 0] * acc.x + g_beta2[c + 0] + bias[c + 0];
    y.y = g_gamma2[c + 1] * acc.y + g_beta2[c + 1] + bias[c + 1];
    y.z = g_gamma2[c + 2] * acc.z + g_beta2[c + 2] + bias[c + 2];
    y.w = g_gamma2[c + 3] * acc.w + g_beta2[c + 3] + bias[c + 3];

    float s1 = y.x + y.y + y.z + y.w;
    float s2 = y.x * y.x + y.y * y.y + y.z * y.z + y.w * y.w;
#pragma unroll
    for (int o = 16; o; o >>= 1) {
        s1 += __shfl_xor_sync(0xffffffffu, s1, o);
        s2 += __shfl_xor_sync(0xffffffffu, s2, o);
    }
    float mu = s1 * (1.0f / 128.0f);
    float var = s2 * (1.0f / 128.0f) - mu * mu;
    float rstd = rsqrtf(var + 1e-5f);
    float4 o4;
    o4.x = (y.x - mu) * rstd;
    o4.y = (y.y - mu) * rstd;
    o4.z = (y.z - mu) * rstd;
    o4.w = (y.w - mu) * rstd;
    *(float4*)&out[(size_t)d * 128 + c] = o4;
}

// ---------------- launch ----------------
extern "C" void kernel_launch(void* const* d_in, const int* in_sizes, int n_in,
                              void* d_out, int out_size)
{
    const float* x       = (const float*)d_in[0];
    const int*   ei      = (const int*)d_in[1];
    const float* conv1_w = (const float*)d_in[2];
    const float* conv1_b = (const float*)d_in[3];
    const float* conv2_w = (const float*)d_in[4];
    const float* conv2_b = (const float*)d_in[5];
    const float* sig_w   = (const float*)d_in[6];
    const float* sig_b   = (const float*)d_in[7];
    const float* fc1_w   = (const float*)d_in[8];
    const float* fc1_b   = (const float*)d_in[9];
    const float* fc2_w   = (const float*)d_in[10];
    const float* fc2_b   = (const float*)d_in[11];
    const float* fc3_w   = (const float*)d_in[12];
    const float* fc3_b   = (const float*)d_in[13];
    const float* fc4_w   = (const float*)d_in[14];
    const float* fc4_b   = (const float*)d_in[15];
    float*       out     = (float*)d_out;

    k_deg_count<<<NEB + NCB, 256>>>(ei, x);
    k_scan1<<<NSB, 1024>>>();
    k_fill<<<(NEDGES + 255) / 256, 256>>>(ei);
    k_agg1<<<NNODES / 8, 256>>>();

    dim3 g256(2, (NNODES + 127) / 128);
    dim3 g128(1, (NNODES + 127) / 128);

    k_gemm<2, 256><<<g256, 256>>>(sig_w, sig_b,
                                  fc1_w, fc1_b, fc2_w, fc2_b,
                                  fc3_w, fc3_b, fc4_w, fc4_b);
    k_gemm<1, 256><<<g256, 256>>>(conv1_w, conv1_b,
                                  nullptr, nullptr, nullptr, nullptr,
                                  nullptr, nullptr, nullptr, nullptr);
    k_gemm<0, 128><<<g128, 256>>>(conv2_w, nullptr,
                                  nullptr, nullptr, nullptr, nullptr,
                                  nullptr, nullptr, nullptr, nullptr);
    k_agg2<<<NNODES / 8 + 64, 256>>>(conv2_b, out);
}